// round 8
// baseline (speedup 1.0000x reference)
#include <cuda_runtime.h>
#include <cuda_bf16.h>
#include <cstdint>
#include <cstddef>

#define SEQ    512
#define BATCH  32
#define IND    1024
#define HID    1024
#define LAYERS 4
#define G4H    (4*HID)
#define SB     (SEQ*BATCH)       // 16384
#define SBH    (SEQ*BATCH*HID)   // 16777216

// ---------------- device scratch (no allocations allowed) ----------------
__device__ float g_gates[(size_t)SB * G4H];      // 256 MB: x-projection + biases per layer
__device__ float g_ybuf[2][SBH];                 // 128 MB: layer output ping-pong
// h state pre-DUPLICATED: hdup[k][b] = (h,h) as u64 -> FFMA2 needs no dup MOVs.
__device__ ulonglong2 g_hdup[2][HID * BATCH / 2];   // [k*16 + b/2], double buffered
__device__ __align__(128) unsigned int g_bar_count;
__device__ __align__(128) unsigned int g_bar_gen;

// ---------------- f32x2 packed-math helpers (sm_103a FFMA2 path) ----------------
typedef unsigned long long u64;

__device__ __forceinline__ u64 pk2(float lo, float hi) {
    u64 r; asm("mov.b64 %0, {%1, %2};" : "=l"(r) : "f"(lo), "f"(hi)); return r;
}
__device__ __forceinline__ u64 dup2(float x) {
    u64 r; asm("mov.b64 %0, {%1, %1};" : "=l"(r) : "f"(x)); return r;
}
__device__ __forceinline__ u64 ffma2(u64 a, u64 b, u64 c) {
    u64 r; asm("fma.rn.f32x2 %0, %1, %2, %3;" : "=l"(r) : "l"(a), "l"(b), "l"(c)); return r;
}
__device__ __forceinline__ u64 fadd2(u64 a, u64 b) {
    u64 r; asm("add.rn.f32x2 %0, %1, %2;" : "=l"(r) : "l"(a), "l"(b)); return r;
}
__device__ __forceinline__ float2 up2(u64 a) {
    float2 v; asm("mov.b64 {%0, %1}, %2;" : "=f"(v.x), "=f"(v.y) : "l"(a)); return v;
}

__device__ __forceinline__ float sigm(float x) { return 1.f / (1.f + expf(-x)); }
__device__ __forceinline__ float tanh_acc(float x) {
    float ax = fabsf(x);
    float e  = expf(-2.f * ax);
    float r  = (1.f - e) / (1.f + e);
    return x >= 0.f ? r : -r;
}

// ---------------- software grid barrier (all CTAs co-resident) ----------------
__device__ __forceinline__ void grid_barrier() {
    __syncthreads();
    if (threadIdx.x == 0) {
        __threadfence();                       // release
        volatile unsigned int* genp = &g_bar_gen;
        unsigned int old_gen = *genp;
        unsigned int arrived = atomicAdd(&g_bar_count, 1u);
        if (arrived == gridDim.x - 1) {
            g_bar_count = 0;
            __threadfence();
            atomicAdd(&g_bar_gen, 1u);
        } else {
            while (*genp == old_gen) { }
        }
        __threadfence();                       // acquire
    }
    __syncthreads();
}

// ================================================================
// Kernel 1: x_gates GEMM.
// C[m][n] = sum_k A[m][k] * W[n][k] + bih[n] + bhh[n]
// 128x128x32 tile, 256 threads, 8x8 microtile via FFMA2.
// __launch_bounds__(256): no min-blocks clause -> ptxas never spills to
// satisfy an occupancy target (acc=64 regs + operands was marginal vs the
// old 128-reg cap). Occ 1-2 both fine for this smem-fed FFMA2 loop.
// ================================================================
__global__ void __launch_bounds__(256)
xgates_gemm(const float* __restrict__ A, const float* __restrict__ W,
            const float* __restrict__ bih, const float* __restrict__ bhh,
            float* __restrict__ C)
{
    __shared__ __align__(16) float As[32][128];
    __shared__ __align__(16) float Bs[32][128];

    const int tid = threadIdx.x;
    const int m0  = blockIdx.y * 128;
    const int n0  = blockIdx.x * 128;
    const int tx  = tid & 15;
    const int ty  = tid >> 4;
    const int lk  = tid & 7;
    const int lm  = tid >> 3;

    const float* Ag = A + (size_t)m0 * IND;
    const float* Wg = W + (size_t)n0 * IND;

    u64 acc[8][4];
#pragma unroll
    for (int m = 0; m < 8; m++)
#pragma unroll
        for (int p = 0; p < 4; p++) acc[m][p] = 0ull;

    for (int k0 = 0; k0 < IND; k0 += 32) {
#pragma unroll
        for (int i = 0; i < 4; i++) {
            int row = lm + i * 32;
            float4 av = *(const float4*)(Ag + (size_t)row * IND + k0 + lk * 4);
            As[lk*4+0][row] = av.x; As[lk*4+1][row] = av.y;
            As[lk*4+2][row] = av.z; As[lk*4+3][row] = av.w;
            float4 wv = *(const float4*)(Wg + (size_t)row * IND + k0 + lk * 4);
            Bs[lk*4+0][row] = wv.x; Bs[lk*4+1][row] = wv.y;
            Bs[lk*4+2][row] = wv.z; Bs[lk*4+3][row] = wv.w;
        }
        __syncthreads();
#pragma unroll
        for (int k = 0; k < 32; k++) {
            float4 a0 = *(const float4*)&As[k][ty * 8];
            float4 a1 = *(const float4*)&As[k][ty * 8 + 4];
            ulonglong2 bA = *(const ulonglong2*)&Bs[k][tx * 8];
            ulonglong2 bB = *(const ulonglong2*)&Bs[k][tx * 8 + 4];
            float am[8] = {a0.x, a0.y, a0.z, a0.w, a1.x, a1.y, a1.z, a1.w};
#pragma unroll
            for (int m = 0; m < 8; m++) {
                u64 ad = dup2(am[m]);
                acc[m][0] = ffma2(ad, bA.x, acc[m][0]);
                acc[m][1] = ffma2(ad, bA.y, acc[m][1]);
                acc[m][2] = ffma2(ad, bB.x, acc[m][2]);
                acc[m][3] = ffma2(ad, bB.y, acc[m][3]);
            }
        }
        __syncthreads();
    }

    float bias[8];
#pragma unroll
    for (int i = 0; i < 8; i++) {
        int n = n0 + tx * 8 + i;
        bias[i] = bih[n] + bhh[n];
    }
#pragma unroll
    for (int m = 0; m < 8; m++) {
        int row = m0 + ty * 8 + m;
        float2 p0 = up2(acc[m][0]);
        float2 p1 = up2(acc[m][1]);
        float2 p2 = up2(acc[m][2]);
        float2 p3 = up2(acc[m][3]);
        float4 o0 = make_float4(p0.x + bias[0], p0.y + bias[1], p1.x + bias[2], p1.y + bias[3]);
        float4 o1 = make_float4(p2.x + bias[4], p2.y + bias[5], p3.x + bias[6], p3.y + bias[7]);
        float* cp = C + (size_t)row * G4H + n0 + tx * 8;
        *(float4*)cp       = o0;
        *(float4*)(cp + 4) = o1;
    }
}

// ================================================================
// Kernel 2: persistent recurrence v2.1.
// 128 CTAs x 512 threads (1 CTA/SM, 4 warps/SMSP).
// CTA owns 8 hidden units; W_hh slice in smem as (Wi,Wf),(Wg,Wo) u64 pairs.
// h arrives PRE-DUPLICATED ((h,h) u64): inner loop = 2xLDG.128 + 1xLDS.128
// + 8xFFMA2 per k, no dup MOVs.
// Reduction scratch padded to stride 33 ulonglong2 per (ks,uu) row —
// conflict-free STS.128 (stride 32 was an 8-way conflict).
// smem = 128KB W + 33KB reduction = 164864 B.
// ================================================================
#define RED_STRIDE 33
#define REC_SMEM (HID*8*16 + 8*8*RED_STRIDE*16)   // 131072 + 33792 = 164864 B

__global__ void __launch_bounds__(512, 1)
lstm_recurrent(const float* __restrict__ gates,   // [512*32*4096]
               const float* __restrict__ Whh,     // [4096*1024]
               float* __restrict__ y,             // [512*32*1024]
               float* __restrict__ hlast,         // [32*1024]
               float* __restrict__ clast)         // [32*1024]
{
    extern __shared__ float smem[];
    ulonglong2* Wsm  = (ulonglong2*)smem;                      // [k*8 + u]
    ulonglong2* red  = (ulonglong2*)(smem + HID * 8 * 4);      // [(ks*8+u)*33 + b]

    const int tid = threadIdx.x;
    const int cta = blockIdx.x;
    const int j0  = cta * 8;

    // preload W_hh slice: Wsm[k][u] = ((Wi,Wf),(Wg,Wo)) for unit j0+u.
    for (int i = tid; i < HID * 8; i += 512) {
        int u = i >> 10, k = i & 1023;
        int j = j0 + u;
        float wi = Whh[(size_t)(0 * HID + j) * HID + k];
        float wf = Whh[(size_t)(1 * HID + j) * HID + k];
        float wg = Whh[(size_t)(2 * HID + j) * HID + k];
        float wo = Whh[(size_t)(3 * HID + j) * HID + k];
        Wsm[k * 8 + u] = make_ulonglong2(pk2(wi, wf), pk2(wg, wo));
    }
    // zero hdup(t=0): 32768 u64 over 128 CTAs x 512 threads
    {
        int idx = cta * 512 + tid;
        if (idx < HID * BATCH) ((u64*)g_hdup[0])[idx] = 0ull;
    }
    grid_barrier();

    // GEMM-phase role
    const int ks = tid >> 6;          // 0..7  (K slice of 128)
    const int uu = tid & 7;           // 0..7  (unit)
    const int bq = (tid >> 3) & 7;    // 0..7  (batch quad: b = bq*4..bq*4+3)
    // pointwise role (tid < 256)
    const int pu = tid & 7;
    const int pb = tid >> 3;          // 0..31
    const int pj = j0 + pu;

    float c_state = 0.f;

    for (int t = 0; t < SEQ; t++) {
        // prefetch x-gate biases (independent of h) — overlaps GEMM phase
        float xg_i = 0.f, xg_f = 0.f, xg_g = 0.f, xg_o = 0.f;
        if (tid < 256) {
            const float* gbase = gates + (size_t)(t * BATCH + pb) * G4H + pj;
            xg_i = gbase[0];
            xg_f = gbase[HID];
            xg_g = gbase[2 * HID];
            xg_o = gbase[3 * HID];
        }

        // partial GEMM over K slice
        const ulonglong2* hd = g_hdup[t & 1];
        u64 aIF0 = 0, aIF1 = 0, aIF2 = 0, aIF3 = 0;
        u64 aGO0 = 0, aGO1 = 0, aGO2 = 0, aGO3 = 0;
        const int kbeg = ks << 7;
#pragma unroll 8
        for (int k = kbeg; k < kbeg + 128; k++) {
            ulonglong2 ha = __ldcg(&hd[k * 16 + bq * 2]);      // b0, b1 (dup pairs)
            ulonglong2 hb = __ldcg(&hd[k * 16 + bq * 2 + 1]);  // b2, b3
            ulonglong2 wv = Wsm[k * 8 + uu];                   // (Wi,Wf),(Wg,Wo)
            aIF0 = ffma2(ha.x, wv.x, aIF0); aGO0 = ffma2(ha.x, wv.y, aGO0);
            aIF1 = ffma2(ha.y, wv.x, aIF1); aGO1 = ffma2(ha.y, wv.y, aGO1);
            aIF2 = ffma2(hb.x, wv.x, aIF2); aGO2 = ffma2(hb.x, wv.y, aGO2);
            aIF3 = ffma2(hb.y, wv.x, aIF3); aGO3 = ffma2(hb.y, wv.y, aGO3);
        }
        {
            ulonglong2* rp = &red[((ks * 8 + uu) * RED_STRIDE) + (bq << 2)];
            rp[0] = make_ulonglong2(aIF0, aGO0);
            rp[1] = make_ulonglong2(aIF1, aGO1);
            rp[2] = make_ulonglong2(aIF2, aGO2);
            rp[3] = make_ulonglong2(aIF3, aGO3);
        }
        __syncthreads();

        // pointwise: reduce 8 K-slices, add x-gates, apply LSTM cell
        if (tid < 256) {
            u64 sIF = pk2(xg_i, xg_f);
            u64 sGO = pk2(xg_g, xg_o);
#pragma unroll
            for (int q = 0; q < 8; q++) {
                ulonglong2 v = red[(q * 8 + pu) * RED_STRIDE + pb];
                sIF = fadd2(sIF, v.x);
                sGO = fadd2(sGO, v.y);
            }
            float2 vif = up2(sIF);
            float2 vgo = up2(sGO);
            float gi = sigm(vif.x), gf = sigm(vif.y);
            float gg = tanh_acc(vgo.x), go = sigm(vgo.y);
            float cn = gf * c_state + gi * gg;
            float hn = go * tanh_acc(cn);
            c_state = cn;

            // single L2-level store of the duplicated h pair
            __stcg((float2*)&((u64*)g_hdup[(t + 1) & 1])[pj * BATCH + pb],
                   make_float2(hn, hn));
            y[(size_t)(t * BATCH + pb) * HID + pj] = hn;
            if (t == SEQ - 1) {
                hlast[pb * HID + pj] = hn;
                clast[pb * HID + pj] = cn;
            }
        }
        grid_barrier();
    }
}

// ================================================================
// Host launch: 4 x (GEMM + persistent recurrence), graph-capturable.
// ================================================================
extern "C" void kernel_launch(void* const* d_in, const int* in_sizes, int n_in,
                              void* d_out, int out_size)
{
    const float* x   = (const float*)d_in[0];
    const float* Wih = (const float*)d_in[1];
    const float* Whh = (const float*)d_in[2];
    const float* bih = (const float*)d_in[3];
    const float* bhh = (const float*)d_in[4];

    float* out    = (float*)d_out;               // [512, 32, 1024]
    float* hstack = out + (size_t)SBH;           // [4, 32, 1024]
    float* cstack = hstack + (size_t)LAYERS * BATCH * HID;

    cudaFuncSetAttribute(lstm_recurrent, cudaFuncAttributeMaxDynamicSharedMemorySize, REC_SMEM);

    void* p;
    cudaGetSymbolAddress(&p, g_gates); float* gates = (float*)p;
    cudaGetSymbolAddress(&p, g_ybuf);  float* ybuf  = (float*)p;

    dim3 ggrid(G4H / 128, SB / 128);  // (32, 128)
    for (int l = 0; l < LAYERS; l++) {
        const float* A = (l == 0) ? x : ybuf + (size_t)((l - 1) & 1) * SBH;
        xgates_gemm<<<ggrid, 256>>>(A,
                                    Wih + (size_t)l * G4H * IND,
                                    bih + (size_t)l * G4H,
                                    bhh + (size_t)l * G4H,
                                    gates);
        float* yt = (l < LAYERS - 1) ? ybuf + (size_t)(l & 1) * SBH : out;
        lstm_recurrent<<<128, 512, REC_SMEM>>>(gates,
                                               Whh + (size_t)l * G4H * HID,
                                               yt,
                                               hstack + (size_t)l * BATCH * HID,
                                               cstack + (size_t)l * BATCH * HID);
    }
}